// round 6
// baseline (speedup 1.0000x reference)
#include <cuda_runtime.h>
#include <cstdint>
#include <cstddef>

#define EMBED    1024
#define NHEADS   16
#define HDIM     64
#define WSIZE    256
#define NWIN     64
#define MTOT     (NWIN*WSIZE)     /* 16384 */
#define LTOT     (MTOT-1)         /* 16383 */
#define QKVN     (3*EMBED)        /* 3072  */

// Scratch (allocation-free rule: __device__ globals)
__device__ float g_qkv[(size_t)MTOT * QKVN];   // gathered-order qkv, [M][3][16][64]
__device__ float g_osc[(size_t)MTOT * EMBED];  // scattered attention output

__device__ __forceinline__ uint32_t f2tf32(float f) {
    uint32_t r;
    asm("cvt.rna.tf32.f32 %0, %1;" : "=r"(r) : "f"(f));
    return r;
}
__device__ __forceinline__ float ex2f(float x) {
    float y;
    asm("ex2.approx.f32 %0, %1;" : "=f"(y) : "f"(x));
    return y;
}
__device__ __forceinline__ void mma_tf32(float* c, const uint32_t* a, const uint32_t* b) {
    asm volatile(
        "mma.sync.aligned.m16n8k8.row.col.f32.tf32.tf32.f32 "
        "{%0,%1,%2,%3}, {%4,%5,%6,%7}, {%8,%9}, {%0,%1,%2,%3};"
        : "+f"(c[0]), "+f"(c[1]), "+f"(c[2]), "+f"(c[3])
        : "r"(a[0]), "r"(a[1]), "r"(a[2]), "r"(a[3]), "r"(b[0]), "r"(b[1]));
}

// ---------------------------------------------------------------------------
// tf32 tensor-core GEMM, fragment-order smem:
//   C[m][n] = sum_k A[row(m)][k] * B[n][k] + bias[n]
//   BM=BN=128, BK=32, 256 threads (8 warps, wm=wid&3, wn=wid>>2), warp 32x64.
//   A tiles stored [tileA(32)][lane(32)][reg(4)] -> one LDS.128 per A-frag.
//   B tiles stored [tileB(64)][lane(32)][reg(2)] -> one LDS.64 per B-frag.
// ---------------------------------------------------------------------------
__global__ void __launch_bounds__(256, 2)
tf32_gemm_kernel(const float* __restrict__ A,
                 const float* __restrict__ B,
                 const float* __restrict__ bias,
                 float* __restrict__ C,
                 const int* __restrict__ gidx,
                 int Mrows, int N, int K, int Avalid)
{
    extern __shared__ float smf[];
    uint32_t* AsF = reinterpret_cast<uint32_t*>(smf);   // [2][32][32][4]
    uint32_t* BsF = AsF + 8192;                          // [2][64][32][2]
    __shared__ int arow[128];

    const int tid  = threadIdx.x;
    const int lane = tid & 31;
    const int wid  = tid >> 5;
    const int wm   = wid & 3;
    const int wn   = wid >> 2;
    const int bm   = blockIdx.y * 128;
    const int bn   = blockIdx.x * 128;

    if (tid < 128) {
        int m = bm + tid;
        int r = -1;
        if (m < Mrows) {
            r = gidx ? gidx[m] : m;
            if (r >= Avalid) r = -1;
        }
        arow[tid] = r;
    }
    __syncthreads();

    const int crow = tid >> 3;            // 0..31 (+i*32)
    const int ckq  = (tid & 7) << 2;      // 0,4,...,28
    const int cks  = ckq >> 3;
    const int ckhi = (ckq >> 2) & 1;

    float4 ra[4], rb[4];

    auto load_regs = [&](int k0) {
        #pragma unroll
        for (int i = 0; i < 4; i++) {
            int row = crow + i * 32;
            int r = arow[row];
            float4 v = make_float4(0.f, 0.f, 0.f, 0.f);
            if (r >= 0)
                v = *reinterpret_cast<const float4*>(&A[(size_t)r * K + k0 + ckq]);
            ra[i] = v;
            rb[i] = *reinterpret_cast<const float4*>(&B[(size_t)(bn + row) * K + k0 + ckq]);
        }
    };

    auto store_tile = [&](int buf) {
        uint32_t* ap = AsF + buf * 4096;
        uint32_t* bp = BsF + buf * 4096;
        #pragma unroll
        for (int i = 0; i < 4; i++) {
            int r   = crow + i * 32;
            int g4_ = r & 7;
            // A: tileA = ((r>>4)*4 + cks), lane = g4*4 + l4, reg = hi + 2*khi
            int hi  = (r >> 3) & 1;
            uint32_t* adst = ap + ((((r >> 4) * 4) + cks) * 128 + g4_ * 16 + hi + 2 * ckhi);
            adst[0]  = f2tf32(ra[i].x);
            adst[4]  = f2tf32(ra[i].y);
            adst[8]  = f2tf32(ra[i].z);
            adst[12] = f2tf32(ra[i].w);
            // B: tileB = ((r>>3)*4 + cks), lane = g4*4 + l4, reg = khi
            uint32_t* bdst = bp + ((((r >> 3) * 4) + cks) * 64 + g4_ * 8 + ckhi);
            bdst[0] = f2tf32(rb[i].x);
            bdst[2] = f2tf32(rb[i].y);
            bdst[4] = f2tf32(rb[i].z);
            bdst[6] = f2tf32(rb[i].w);
        }
    };

    float acc[2][8][4];
    #pragma unroll
    for (int mt = 0; mt < 2; mt++)
        #pragma unroll
        for (int nt = 0; nt < 8; nt++)
            #pragma unroll
            for (int i = 0; i < 4; i++) acc[mt][nt][i] = 0.f;

    const int g4 = lane >> 2;
    const int l4 = lane & 3;

    load_regs(0);
    store_tile(0);
    __syncthreads();

    const int T = K / 32;
    for (int kt = 0; kt < T; kt++) {
        if (kt + 1 < T) load_regs((kt + 1) * 32);

        const uint32_t* ap = AsF + (kt & 1) * 4096 + (wm * 8) * 128 + lane * 4;
        const uint32_t* bp = BsF + (kt & 1) * 4096 + (wn * 32) * 64 + lane * 2;

        #pragma unroll
        for (int ks = 0; ks < 4; ks++) {
            uint32_t afr[2][4], bfr[8][2];
            #pragma unroll
            for (int mt = 0; mt < 2; mt++)
                *reinterpret_cast<uint4*>(afr[mt]) =
                    *reinterpret_cast<const uint4*>(ap + (mt * 4 + ks) * 128);
            #pragma unroll
            for (int nt = 0; nt < 8; nt++)
                *reinterpret_cast<uint2*>(bfr[nt]) =
                    *reinterpret_cast<const uint2*>(bp + (nt * 4 + ks) * 64);
            #pragma unroll
            for (int mt = 0; mt < 2; mt++)
                #pragma unroll
                for (int nt = 0; nt < 8; nt++)
                    mma_tf32(acc[mt][nt], afr[mt], bfr[nt]);
        }

        if (kt + 1 < T) {
            store_tile((kt + 1) & 1);
            __syncthreads();
        }
    }

    #pragma unroll
    for (int nt = 0; nt < 8; nt++) {
        int col = bn + wn * 64 + nt * 8 + l4 * 2;
        float b0 = bias[col], b1 = bias[col + 1];
        #pragma unroll
        for (int mt = 0; mt < 2; mt++) {
            int row = bm + wm * 32 + mt * 16 + g4;
            if (row < Mrows) {
                float2 v = make_float2(acc[mt][nt][0] + b0, acc[mt][nt][1] + b1);
                *reinterpret_cast<float2*>(&C[(size_t)row * N + col]) = v;
            }
            if (row + 8 < Mrows) {
                float2 v = make_float2(acc[mt][nt][2] + b0, acc[mt][nt][3] + b1);
                *reinterpret_cast<float2*>(&C[(size_t)(row + 8) * N + col]) = v;
            }
        }
    }
}

// ---------------------------------------------------------------------------
// Tensor-core flash attention, 512 threads (16 warps), warp owns 16 Q rows.
// Smem (tf32 bits): Ks[256][68] roped-K, Vt[64][260] V^T, Pb[256][68]
// (Q staging, then per-warp P). Online softmax in log2 domain.
// ---------------------------------------------------------------------------
#define KS_STR 68
#define VT_STR 260
#define PB_STR 68
#define KS_OFF 0
#define VT_OFF (WSIZE * KS_STR)            /* 17408 */
#define PB_OFF (VT_OFF + HDIM * VT_STR)    /* 34048 */
#define ATTN_SMEM_F (PB_OFF + WSIZE * PB_STR)  /* 51456 floats = 205824 B */

__global__ void __launch_bounds__(512)
attn_tc_kernel(const float* __restrict__ qkv,
               const float* __restrict__ cosb,
               const float* __restrict__ sinb,
               const int* __restrict__ kvidx,
               float* __restrict__ osc)
{
    extern __shared__ float shf[];
    uint32_t* sh = reinterpret_cast<uint32_t*>(shf);
    uint32_t* Ks = sh + KS_OFF;
    uint32_t* Vt = sh + VT_OFF;
    uint32_t* Pb = sh + PB_OFF;

    const int w    = blockIdx.x;
    const int h    = blockIdx.y;
    const int tid  = threadIdx.x;
    const int lane = tid & 31;
    const int wid  = tid >> 5;          // 0..15
    const int g4   = lane >> 2;
    const int l4   = lane & 3;
    const int wrow = wid * 16;

    // ---- stage roped K, V^T, roped Q (into Pb) as tf32; 2 threads per row ----
    {
        const int row = tid >> 1;
        const int d0  = (tid & 1) * 16;
        const int gi  = w * WSIZE + row;
        const float* qrow = &qkv[(size_t)gi * QKVN + h * HDIM];
        const float* krow = qrow + EMBED;
        const float* vrow = qrow + 2 * EMBED;
        const float* crw  = &cosb[(size_t)gi * HDIM];
        const float* srw  = &sinb[(size_t)gi * HDIM];
        #pragma unroll
        for (int dd = 0; dd < 16; dd++) {
            int d = d0 + dd;
            float c0 = crw[d], s0 = srw[d];
            float q0 = qrow[d], q1 = qrow[d+32];
            float k0 = krow[d], k1 = krow[d+32];
            Pb[row * PB_STR + d]      = f2tf32(q0*c0 - q1*s0);
            Pb[row * PB_STR + d + 32] = f2tf32(q1*c0 + q0*s0);
            Ks[row * KS_STR + d]      = f2tf32(k0*c0 - k1*s0);
            Ks[row * KS_STR + d + 32] = f2tf32(k1*c0 + k0*s0);
            Vt[(d)      * VT_STR + row] = f2tf32(vrow[d]);
            Vt[(d + 32) * VT_STR + row] = f2tf32(vrow[d+32]);
        }
    }
    __syncthreads();

    // ---- load Q fragments (m16k8) from own Pb rows ----
    uint32_t aQ[8][4];
    {
        int r0 = wrow + g4;
        #pragma unroll
        for (int k8 = 0; k8 < 8; k8++) {
            aQ[k8][0] = Pb[(r0    ) * PB_STR + k8*8 + l4];
            aQ[k8][1] = Pb[(r0 + 8) * PB_STR + k8*8 + l4];
            aQ[k8][2] = Pb[(r0    ) * PB_STR + k8*8 + 4 + l4];
            aQ[k8][3] = Pb[(r0 + 8) * PB_STR + k8*8 + 4 + l4];
        }
    }
    __syncwarp();

    const float SC = 0.125f * 1.4426950408889634f;   // scale * log2(e)

    float mx[2] = {-1e30f, -1e30f}, lsum[2] = {0.f, 0.f};
    float Oacc[8][4];
    #pragma unroll
    for (int nt = 0; nt < 8; nt++)
        #pragma unroll
        for (int i = 0; i < 4; i++) Oacc[nt][i] = 0.f;

    for (int c = 0; c < 4; c++) {
        const int n0 = c * 64;

        // ---- S = Q K^T chunk [16 x 64] ----
        float Sacc[8][4];
        #pragma unroll
        for (int nt = 0; nt < 8; nt++)
            #pragma unroll
            for (int i = 0; i < 4; i++) Sacc[nt][i] = 0.f;

        #pragma unroll
        for (int k8 = 0; k8 < 8; k8++) {
            uint32_t bf[8][2];
            #pragma unroll
            for (int nt = 0; nt < 8; nt++) {
                int n = n0 + nt * 8 + g4;
                bf[nt][0] = Ks[n * KS_STR + k8*8 + l4];
                bf[nt][1] = Ks[n * KS_STR + k8*8 + 4 + l4];
            }
            #pragma unroll
            for (int nt = 0; nt < 8; nt++)
                mma_tf32(Sacc[nt], aQ[k8], bf[nt]);
        }

        // ---- online softmax (log2 domain) ----
        #pragma unroll
        for (int hf = 0; hf < 2; hf++) {
            float rm = -1e30f;
            #pragma unroll
            for (int nt = 0; nt < 8; nt++) {
                rm = fmaxf(rm, Sacc[nt][2*hf]);
                rm = fmaxf(rm, Sacc[nt][2*hf+1]);
            }
            rm = fmaxf(rm, __shfl_xor_sync(0xffffffffu, rm, 1));
            rm = fmaxf(rm, __shfl_xor_sync(0xffffffffu, rm, 2));
            float nmx = fmaxf(mx[hf], rm * SC);
            float corr = ex2f(mx[hf] - nmx);
            mx[hf] = nmx;

            float ps = 0.f;
            #pragma unroll
            for (int nt = 0; nt < 8; nt++) {
                float p0 = ex2f(fmaf(Sacc[nt][2*hf],   SC, -nmx));
                float p1 = ex2f(fmaf(Sacc[nt][2*hf+1], SC, -nmx));
                ps += p0 + p1;
                Sacc[nt][2*hf]   = p0;
                Sacc[nt][2*hf+1] = p1;
            }
            ps += __shfl_xor_sync(0xffffffffu, ps, 1);
            ps += __shfl_xor_sync(0xffffffffu, ps, 2);
            lsum[hf] = lsum[hf] * corr + ps;

            #pragma unroll
            for (int nt = 0; nt < 8; nt++) {
                Oacc[nt][2*hf]   *= corr;
                Oacc[nt][2*hf+1] *= corr;
            }
        }

        // ---- write P (tf32) to own Pb rows ----
        {
            int r0 = wrow + g4;
            #pragma unroll
            for (int nt = 0; nt < 8; nt++) {
                int col = nt * 8 + 2 * l4;
                Pb[(r0    ) * PB_STR + col    ] = f2tf32(Sacc[nt][0]);
                Pb[(r0    ) * PB_STR + col + 1] = f2tf32(Sacc[nt][1]);
                Pb[(r0 + 8) * PB_STR + col    ] = f2tf32(Sacc[nt][2]);
                Pb[(r0 + 8) * PB_STR + col + 1] = f2tf32(Sacc[nt][3]);
            }
        }
        __syncwarp();

        // ---- O += P V chunk ----
        #pragma unroll
        for (int k8 = 0; k8 < 8; k8++) {
            uint32_t aP[4];
            int r0 = wrow + g4;
            aP[0] = Pb[(r0    ) * PB_STR + k8*8 + l4];
            aP[1] = Pb[(r0 + 8) * PB_STR + k8*8 + l4];
            aP[2] = Pb[(r0    ) * PB_STR + k8*8 + 4 + l4];
            aP[3] = Pb[(r0 + 8) * PB_STR + k8*8 + 4 + l4];
            uint32_t bv[8][2];
            #pragma unroll
            for (int nt = 0; nt < 8; nt++) {
                int n = nt * 8 + g4;
                bv[nt][0] = Vt[n * VT_STR + n0 + k8*8 + l4];
                bv[nt][1] = Vt[n * VT_STR + n0 + k8*8 + 4 + l4];
            }
            #pragma unroll
            for (int nt = 0; nt < 8; nt++)
                mma_tf32(Oacc[nt], aP, bv[nt]);
        }
        __syncwarp();
    }

    // ---- epilogue: normalize + scattered store ----
    {
        int r0 = wrow + g4;
        float inv0 = 1.f / lsum[0];
        float inv1 = 1.f / lsum[1];
        int o0 = kvidx[w * WSIZE + r0];
        int o1 = kvidx[w * WSIZE + r0 + 8];
        float* base0 = &osc[(size_t)o0 * EMBED + h * HDIM];
        float* base1 = &osc[(size_t)o1 * EMBED + h * HDIM];
        #pragma unroll
        for (int nt = 0; nt < 8; nt++) {
            int col = nt * 8 + 2 * l4;
            float2 v0 = make_float2(Oacc[nt][0] * inv0, Oacc[nt][1] * inv0);
            float2 v1 = make_float2(Oacc[nt][2] * inv1, Oacc[nt][3] * inv1);
            *reinterpret_cast<float2*>(&base0[col]) = v0;
            *reinterpret_cast<float2*>(&base1[col]) = v1;
        }
    }
}

// ---------------------------------------------------------------------------
extern "C" void kernel_launch(void* const* d_in, const int* in_sizes, int n_in,
                              void* d_out, int out_size)
{
    const float* x      = (const float*)d_in[0];
    const float* qkv_w  = (const float*)d_in[1];
    const float* qkv_b  = (const float*)d_in[2];
    const float* proj_w = (const float*)d_in[3];
    const float* proj_b = (const float*)d_in[4];
    const float* rope_c = (const float*)d_in[6];
    const float* rope_s = (const float*)d_in[7];
    const int*   kvi    = (const int*)d_in[8];
    float*       out    = (float*)d_out;

    float *qkv_buf = nullptr, *osc_buf = nullptr;
    cudaGetSymbolAddress((void**)&qkv_buf, g_qkv);
    cudaGetSymbolAddress((void**)&osc_buf, g_osc);

    const int gemm_smem = 16384 * (int)sizeof(float);   // 64 KB
    cudaFuncSetAttribute(tf32_gemm_kernel,
                         cudaFuncAttributeMaxDynamicSharedMemorySize, gemm_smem);

    // 1) QKV GEMM with fused row gather
    {
        dim3 grid(QKVN / 128, MTOT / 128);
        tf32_gemm_kernel<<<grid, 256, gemm_smem>>>(x, qkv_w, qkv_b, qkv_buf, kvi,
                                                   MTOT, QKVN, EMBED, LTOT);
    }

    // 2) Tensor-core flash attention (RoPE + scatter fused)
    {
        int shmem = ATTN_SMEM_F * (int)sizeof(float);   // 205824 B
        cudaFuncSetAttribute(attn_tc_kernel,
                             cudaFuncAttributeMaxDynamicSharedMemorySize, shmem);
        dim3 grid(NWIN, NHEADS);
        attn_tc_kernel<<<grid, 512, shmem>>>(qkv_buf, rope_c, rope_s, kvi, osc_buf);
    }

    // 3) Output projection
    {
        dim3 grid(EMBED / 128, (LTOT + 127) / 128);
        tf32_gemm_kernel<<<grid, 256, gemm_smem>>>(osc_buf, proj_w, proj_b, out, nullptr,
                                                   LTOT, EMBED, EMBED, MTOT);
    }
}

// round 7
// speedup vs baseline: 1.4406x; 1.4406x over previous
#include <cuda_runtime.h>
#include <cstdint>
#include <cstddef>

#define EMBED    1024
#define NHEADS   16
#define HDIM     64
#define WSIZE    256
#define NWIN     64
#define MTOT     (NWIN*WSIZE)     /* 16384 */
#define LTOT     (MTOT-1)         /* 16383 */
#define QKVN     (3*EMBED)        /* 3072  */

// Scratch (allocation-free rule: __device__ globals)
__device__ float g_qkv[(size_t)MTOT * QKVN];   // gathered-order qkv, [M][3][16][64]
__device__ float g_osc[(size_t)MTOT * EMBED];  // scattered attention output

__device__ __forceinline__ uint32_t f2tf32(float f) {
    uint32_t r;
    asm("cvt.rna.tf32.f32 %0, %1;" : "=r"(r) : "f"(f));
    return r;
}
__device__ __forceinline__ float ex2f(float x) {
    float y;
    asm("ex2.approx.f32 %0, %1;" : "=f"(y) : "f"(x));
    return y;
}
__device__ __forceinline__ void mma_tf32(float* c, const uint32_t* a, const uint32_t* b) {
    asm volatile(
        "mma.sync.aligned.m16n8k8.row.col.f32.tf32.tf32.f32 "
        "{%0,%1,%2,%3}, {%4,%5,%6,%7}, {%8,%9}, {%0,%1,%2,%3};"
        : "+f"(c[0]), "+f"(c[1]), "+f"(c[2]), "+f"(c[3])
        : "r"(a[0]), "r"(a[1]), "r"(a[2]), "r"(a[3]), "r"(b[0]), "r"(b[1]));
}
__device__ __forceinline__ void ldsm_x4(uint32_t* r, uint32_t addr) {
    asm volatile("ldmatrix.sync.aligned.m8n8.x4.shared.b16 {%0,%1,%2,%3}, [%4];"
                 : "=r"(r[0]), "=r"(r[1]), "=r"(r[2]), "=r"(r[3]) : "r"(addr));
}
__device__ __forceinline__ uint32_t smem_u32(const void* p) {
    uint32_t a;
    asm("{ .reg .u64 t; cvta.to.shared.u64 t, %1; cvt.u32.u64 %0, t; }"
        : "=r"(a) : "l"(p));
    return a;
}

// ---------------------------------------------------------------------------
// tf32 tensor-core GEMM:  C[m][n] = sum_k A[row(m)][k] * B[n][k] + bias[n]
//   BM=BN=128, BK=32, 256 threads (8 warps, 4x2), warp tile 32x64.
//   Stride-36 smem tiles, STS.128 stores, ldmatrix.x4 fragment loads.
// ---------------------------------------------------------------------------
#define TSTRIDE 36
#define TILE_F  (128 * TSTRIDE)

__global__ void __launch_bounds__(256, 2)
tf32_gemm_kernel(const float* __restrict__ A,
                 const float* __restrict__ B,
                 const float* __restrict__ bias,
                 float* __restrict__ C,
                 const int* __restrict__ gidx,
                 int Mrows, int N, int K, int Avalid)
{
    extern __shared__ float sm[];
    float* As = sm;                 // [2][128][36]
    float* Bs = sm + 2 * TILE_F;    // [2][128][36]
    __shared__ int arow[128];

    const int tid  = threadIdx.x;
    const int lane = tid & 31;
    const int wid  = tid >> 5;
    const int wm   = wid & 3;
    const int wn   = wid >> 2;
    const int bm   = blockIdx.y * 128;
    const int bn   = blockIdx.x * 128;

    if (tid < 128) {
        int m = bm + tid;
        int r = -1;
        if (m < Mrows) {
            r = gidx ? gidx[m] : m;
            if (r >= Avalid) r = -1;
        }
        arow[tid] = r;
    }
    __syncthreads();

    const int crow = tid >> 3;
    const int ckq  = (tid & 7) << 2;

    float4 ra[4], rb[4];

    auto load_regs = [&](int k0) {
        #pragma unroll
        for (int i = 0; i < 4; i++) {
            int row = crow + i * 32;
            int r = arow[row];
            float4 v = make_float4(0.f, 0.f, 0.f, 0.f);
            if (r >= 0)
                v = *reinterpret_cast<const float4*>(&A[(size_t)r * K + k0 + ckq]);
            ra[i] = v;
            rb[i] = *reinterpret_cast<const float4*>(&B[(size_t)(bn + row) * K + k0 + ckq]);
        }
    };

    auto store_tile = [&](int buf) {
        float* ap = As + buf * TILE_F;
        float* bp = Bs + buf * TILE_F;
        #pragma unroll
        for (int i = 0; i < 4; i++) {
            int row = crow + i * 32;
            uint32_t* a4 = reinterpret_cast<uint32_t*>(&ap[row * TSTRIDE + ckq]);
            a4[0] = f2tf32(ra[i].x); a4[1] = f2tf32(ra[i].y);
            a4[2] = f2tf32(ra[i].z); a4[3] = f2tf32(ra[i].w);
            uint32_t* b4 = reinterpret_cast<uint32_t*>(&bp[row * TSTRIDE + ckq]);
            b4[0] = f2tf32(rb[i].x); b4[1] = f2tf32(rb[i].y);
            b4[2] = f2tf32(rb[i].z); b4[3] = f2tf32(rb[i].w);
        }
    };

    float acc[2][8][4];
    #pragma unroll
    for (int mt = 0; mt < 2; mt++)
        #pragma unroll
        for (int nt = 0; nt < 8; nt++)
            #pragma unroll
            for (int i = 0; i < 4; i++) acc[mt][nt][i] = 0.f;

    const int g4 = lane >> 2;
    const int l4 = lane & 3;

    // ldmatrix per-lane byte addresses
    // A-frag: row = wm*32 + (lane&15) (+mt*16), col = (lane>>4)*4 (+ks*8)
    // B-frag pair: row = wn*64 + (lane>>4)*8 + (lane&7) (+ntp*16),
    //              col = ((lane>>3)&1)*4 (+ks*8)
    const uint32_t smb = smem_u32(sm);
    const uint32_t aL = smb +
        (((wm * 32 + (lane & 15)) * TSTRIDE + ((lane >> 4) << 2)) << 2);
    const uint32_t bL = smb + (2 * TILE_F << 2) +
        (((wn * 64 + ((lane >> 4) << 3) + (lane & 7)) * TSTRIDE + (((lane >> 3) & 1) << 2)) << 2);
    const uint32_t BUFB = TILE_F << 2;        // bytes per buffer
    const uint32_t MT16 = 16 * TSTRIDE << 2;  // 16 rows in bytes (2304)

    load_regs(0);
    store_tile(0);
    __syncthreads();

    const int T = K / 32;
    for (int kt = 0; kt < T; kt++) {
        if (kt + 1 < T) load_regs((kt + 1) * 32);

        const uint32_t ab = aL + (kt & 1) * BUFB;
        const uint32_t bb = bL + (kt & 1) * BUFB;

        #pragma unroll
        for (int ks = 0; ks < 4; ks++) {
            uint32_t afr[2][4], bfr[16];
            ldsm_x4(afr[0], ab + ks * 32);
            ldsm_x4(afr[1], ab + MT16 + ks * 32);
            #pragma unroll
            for (int ntp = 0; ntp < 4; ntp++)
                ldsm_x4(&bfr[ntp * 4], bb + ntp * MT16 + ks * 32);
            #pragma unroll
            for (int mt = 0; mt < 2; mt++)
                #pragma unroll
                for (int nt = 0; nt < 8; nt++)
                    mma_tf32(acc[mt][nt], afr[mt], &bfr[nt * 2]);
        }

        if (kt + 1 < T) {
            store_tile((kt + 1) & 1);
            __syncthreads();
        }
    }

    #pragma unroll
    for (int nt = 0; nt < 8; nt++) {
        int col = bn + wn * 64 + nt * 8 + l4 * 2;
        float b0 = bias[col], b1 = bias[col + 1];
        #pragma unroll
        for (int mt = 0; mt < 2; mt++) {
            int row = bm + wm * 32 + mt * 16 + g4;
            if (row < Mrows) {
                float2 v = make_float2(acc[mt][nt][0] + b0, acc[mt][nt][1] + b1);
                *reinterpret_cast<float2*>(&C[(size_t)row * N + col]) = v;
            }
            if (row + 8 < Mrows) {
                float2 v = make_float2(acc[mt][nt][2] + b0, acc[mt][nt][3] + b1);
                *reinterpret_cast<float2*>(&C[(size_t)(row + 8) * N + col]) = v;
            }
        }
    }
}

// ---------------------------------------------------------------------------
// Tensor-core flash attention, 512 threads (16 warps), warp owns 16 Q rows.
// Smem (tf32 bits): Ks[256][68] roped-K, Vt[64][260] V^T, Pb[256][68]
// (Q staging, then per-warp P). ldmatrix fragment loads throughout.
// ---------------------------------------------------------------------------
#define KS_STR 68
#define VT_STR 260
#define PB_STR 68
#define KS_OFF 0
#define VT_OFF (WSIZE * KS_STR)            /* 17408 */
#define PB_OFF (VT_OFF + HDIM * VT_STR)    /* 34048 */
#define ATTN_SMEM_F (PB_OFF + WSIZE * PB_STR)  /* 51456 floats = 205824 B */

__global__ void __launch_bounds__(512)
attn_tc_kernel(const float* __restrict__ qkv,
               const float* __restrict__ cosb,
               const float* __restrict__ sinb,
               const int* __restrict__ kvidx,
               float* __restrict__ osc)
{
    extern __shared__ float shf[];
    uint32_t* sh = reinterpret_cast<uint32_t*>(shf);
    uint32_t* Ks = sh + KS_OFF;
    uint32_t* Vt = sh + VT_OFF;
    uint32_t* Pb = sh + PB_OFF;

    const int w    = blockIdx.x;
    const int h    = blockIdx.y;
    const int tid  = threadIdx.x;
    const int lane = tid & 31;
    const int wid  = tid >> 5;          // 0..15
    const int g4   = lane >> 2;
    const int l4   = lane & 3;
    const int wrow = wid * 16;

    // ---- stage roped K, V^T, roped Q (into Pb) as tf32; 2 threads per row ----
    {
        const int row = tid >> 1;
        const int d0  = (tid & 1) * 16;
        const int gi  = w * WSIZE + row;
        const float* qrow = &qkv[(size_t)gi * QKVN + h * HDIM];
        const float* krow = qrow + EMBED;
        const float* vrow = qrow + 2 * EMBED;
        const float* crw  = &cosb[(size_t)gi * HDIM];
        const float* srw  = &sinb[(size_t)gi * HDIM];
        #pragma unroll
        for (int dd = 0; dd < 16; dd++) {
            int d = d0 + dd;
            float c0 = crw[d], s0 = srw[d];
            float q0 = qrow[d], q1 = qrow[d+32];
            float k0 = krow[d], k1 = krow[d+32];
            Pb[row * PB_STR + d]      = f2tf32(q0*c0 - q1*s0);
            Pb[row * PB_STR + d + 32] = f2tf32(q1*c0 + q0*s0);
            Ks[row * KS_STR + d]      = f2tf32(k0*c0 - k1*s0);
            Ks[row * KS_STR + d + 32] = f2tf32(k1*c0 + k0*s0);
            Vt[(d)      * VT_STR + row] = f2tf32(vrow[d]);
            Vt[(d + 32) * VT_STR + row] = f2tf32(vrow[d+32]);
        }
    }
    __syncthreads();

    // ldmatrix per-lane byte addresses
    const uint32_t ks_u = smem_u32(Ks);
    const uint32_t vt_u = smem_u32(Vt);
    const uint32_t pb_u = smem_u32(Pb);
    // A-frag from Pb: row = wrow + (lane&15), col = (lane>>4)*4 (+k8*8)
    const uint32_t pbA = pb_u +
        (((wrow + (lane & 15)) * PB_STR + ((lane >> 4) << 2)) << 2);
    // B-frag pair from Ks: row = (lane>>4)*8 + (lane&7) (+n0 + ntp*16),
    //                      col = ((lane>>3)&1)*4 (+k8*8)
    const uint32_t ksB = ks_u +
        (((((lane >> 4) << 3) + (lane & 7)) * KS_STR + (((lane >> 3) & 1) << 2)) << 2);
    // B-frag pair from Vt: row = (lane>>4)*8 + (lane&7) (+ntp*16), col = n0 + k8*8
    const uint32_t vtB = vt_u +
        (((((lane >> 4) << 3) + (lane & 7)) * VT_STR + (((lane >> 3) & 1) << 2)) << 2);

    // ---- load Q fragments (m16k8) ----
    uint32_t aQ[8][4];
    #pragma unroll
    for (int k8 = 0; k8 < 8; k8++)
        ldsm_x4(aQ[k8], pbA + k8 * 32);
    __syncwarp();

    const float SC = 0.125f * 1.4426950408889634f;   // scale * log2(e)

    float mx[2] = {-1e30f, -1e30f}, lsum[2] = {0.f, 0.f};
    float Oacc[8][4];
    #pragma unroll
    for (int nt = 0; nt < 8; nt++)
        #pragma unroll
        for (int i = 0; i < 4; i++) Oacc[nt][i] = 0.f;

    for (int c = 0; c < 4; c++) {
        const int n0 = c * 64;

        // ---- S = Q K^T chunk [16 x 64] ----
        float Sacc[8][4];
        #pragma unroll
        for (int nt = 0; nt < 8; nt++)
            #pragma unroll
            for (int i = 0; i < 4; i++) Sacc[nt][i] = 0.f;

        #pragma unroll
        for (int k8 = 0; k8 < 8; k8++) {
            uint32_t bf[16];
            #pragma unroll
            for (int ntp = 0; ntp < 4; ntp++)
                ldsm_x4(&bf[ntp * 4],
                        ksB + ((n0 + ntp * 16) * KS_STR << 2) + k8 * 32);
            #pragma unroll
            for (int nt = 0; nt < 8; nt++)
                mma_tf32(Sacc[nt], aQ[k8], &bf[nt * 2]);
        }

        // ---- online softmax (log2 domain) ----
        #pragma unroll
        for (int hf = 0; hf < 2; hf++) {
            float rm = -1e30f;
            #pragma unroll
            for (int nt = 0; nt < 8; nt++) {
                rm = fmaxf(rm, Sacc[nt][2*hf]);
                rm = fmaxf(rm, Sacc[nt][2*hf+1]);
            }
            rm = fmaxf(rm, __shfl_xor_sync(0xffffffffu, rm, 1));
            rm = fmaxf(rm, __shfl_xor_sync(0xffffffffu, rm, 2));
            float nmx = fmaxf(mx[hf], rm * SC);
            float corr = ex2f(mx[hf] - nmx);
            mx[hf] = nmx;

            float ps = 0.f;
            #pragma unroll
            for (int nt = 0; nt < 8; nt++) {
                float p0 = ex2f(fmaf(Sacc[nt][2*hf],   SC, -nmx));
                float p1 = ex2f(fmaf(Sacc[nt][2*hf+1], SC, -nmx));
                ps += p0 + p1;
                Sacc[nt][2*hf]   = p0;
                Sacc[nt][2*hf+1] = p1;
            }
            ps += __shfl_xor_sync(0xffffffffu, ps, 1);
            ps += __shfl_xor_sync(0xffffffffu, ps, 2);
            lsum[hf] = lsum[hf] * corr + ps;

            #pragma unroll
            for (int nt = 0; nt < 8; nt++) {
                Oacc[nt][2*hf]   *= corr;
                Oacc[nt][2*hf+1] *= corr;
            }
        }

        // ---- write P (tf32) to own Pb rows ----
        {
            int r0 = wrow + g4;
            #pragma unroll
            for (int nt = 0; nt < 8; nt++) {
                int col = nt * 8 + 2 * l4;
                Pb[(r0    ) * PB_STR + col    ] = f2tf32(Sacc[nt][0]);
                Pb[(r0    ) * PB_STR + col + 1] = f2tf32(Sacc[nt][1]);
                Pb[(r0 + 8) * PB_STR + col    ] = f2tf32(Sacc[nt][2]);
                Pb[(r0 + 8) * PB_STR + col + 1] = f2tf32(Sacc[nt][3]);
            }
        }
        __syncwarp();

        // ---- O += P V chunk ----
        #pragma unroll
        for (int k8 = 0; k8 < 8; k8++) {
            uint32_t aP[4], bv[16];
            ldsm_x4(aP, pbA + k8 * 32);
            #pragma unroll
            for (int ntp = 0; ntp < 4; ntp++)
                ldsm_x4(&bv[ntp * 4],
                        vtB + (ntp * 16 * VT_STR << 2) + ((n0 + k8 * 8) << 2));
            #pragma unroll
            for (int nt = 0; nt < 8; nt++)
                mma_tf32(Oacc[nt], aP, &bv[nt * 2]);
        }
        __syncwarp();
    }

    // ---- epilogue: normalize + scattered store ----
    {
        int r0 = wrow + g4;
        float inv0 = 1.f / lsum[0];
        float inv1 = 1.f / lsum[1];
        int o0 = kvidx[w * WSIZE + r0];
        int o1 = kvidx[w * WSIZE + r0 + 8];
        float* base0 = &osc[(size_t)o0 * EMBED + h * HDIM];
        float* base1 = &osc[(size_t)o1 * EMBED + h * HDIM];
        #pragma unroll
        for (int nt = 0; nt < 8; nt++) {
            int col = nt * 8 + 2 * l4;
            float2 v0 = make_float2(Oacc[nt][0] * inv0, Oacc[nt][1] * inv0);
            float2 v1 = make_float2(Oacc[nt][2] * inv1, Oacc[nt][3] * inv1);
            *reinterpret_cast<float2*>(&base0[col]) = v0;
            *reinterpret_cast<float2*>(&base1[col]) = v1;
        }
    }
}

// ---------------------------------------------------------------------------
extern "C" void kernel_launch(void* const* d_in, const int* in_sizes, int n_in,
                              void* d_out, int out_size)
{
    const float* x      = (const float*)d_in[0];
    const float* qkv_w  = (const float*)d_in[1];
    const float* qkv_b  = (const float*)d_in[2];
    const float* proj_w = (const float*)d_in[3];
    const float* proj_b = (const float*)d_in[4];
    const float* rope_c = (const float*)d_in[6];
    const float* rope_s = (const float*)d_in[7];
    const int*   kvi    = (const int*)d_in[8];
    float*       out    = (float*)d_out;

    float *qkv_buf = nullptr, *osc_buf = nullptr;
    cudaGetSymbolAddress((void**)&qkv_buf, g_qkv);
    cudaGetSymbolAddress((void**)&osc_buf, g_osc);

    const int gemm_smem = 4 * TILE_F * (int)sizeof(float);   // 73728 B
    cudaFuncSetAttribute(tf32_gemm_kernel,
                         cudaFuncAttributeMaxDynamicSharedMemorySize, gemm_smem);

    // 1) QKV GEMM with fused row gather
    {
        dim3 grid(QKVN / 128, MTOT / 128);
        tf32_gemm_kernel<<<grid, 256, gemm_smem>>>(x, qkv_w, qkv_b, qkv_buf, kvi,
                                                   MTOT, QKVN, EMBED, LTOT);
    }

    // 2) Tensor-core flash attention (RoPE + scatter fused)
    {
        int shmem = ATTN_SMEM_F * (int)sizeof(float);   // 205824 B
        cudaFuncSetAttribute(attn_tc_kernel,
                             cudaFuncAttributeMaxDynamicSharedMemorySize, shmem);
        dim3 grid(NWIN, NHEADS);
        attn_tc_kernel<<<grid, 512, shmem>>>(qkv_buf, rope_c, rope_s, kvi, osc_buf);
    }

    // 3) Output projection
    {
        dim3 grid(EMBED / 128, (LTOT + 127) / 128);
        tf32_gemm_kernel<<<grid, 256, gemm_smem>>>(osc_buf, proj_w, proj_b, out, nullptr,
                                                   LTOT, EMBED, EMBED, MTOT);
    }
}